// round 4
// baseline (speedup 1.0000x reference)
#include <cuda_runtime.h>
#include <mma.h>
#include <cstdint>

using namespace nvcuda;

#define Ecfg 1024
#define Hh   16
#define HKV  4
#define Dd   64

#define BM  128
#define BN  128
#define LDA 40
#define LDK 72

// ---------------- scratch (device globals) ----------------
__device__ float g_qraw[2 * 2048 * 1024];
__device__ float g_kraw[2 * 2048 * 256];
__device__ float g_vraw[2 * 2048 * 256];
__device__ float g_qt  [2 * 16 * 2048 * 64];
__device__ float g_kt  [2 * 4  * 2048 * 64];
__device__ float g_vt  [2 * 4  * 2048 * 64];
__device__ float g_attn[2 * 2048 * 1024];
__device__ float g_xtf [2 * 2048 * 1024];
__device__ float g_wqt [1024 * 1024];
__device__ float g_wkt [256 * 1024];
__device__ float g_wvt [256 * 1024];
__device__ float g_wpt [1024 * 1024];

// ---------------- cp.async helpers ----------------
__device__ __forceinline__ void cp16(float* smem_dst, const float* gsrc) {
    uint32_t s = (uint32_t)__cvta_generic_to_shared(smem_dst);
    asm volatile("cp.async.cg.shared.global [%0], [%1], 16;\n" :: "r"(s), "l"(gsrc));
}
#define CP_COMMIT() asm volatile("cp.async.commit_group;\n" ::: "memory")
#define CP_WAIT1()  asm volatile("cp.async.wait_group 1;\n" ::: "memory")
#define CP_WAIT0()  asm volatile("cp.async.wait_group 0;\n" ::: "memory")

// ---------------- tf32 convert (values pre-rounded once) ----------------
__global__ void cvt_tf32(const float* __restrict__ in, float* __restrict__ out, int n4) {
    int i = blockIdx.x * blockDim.x + threadIdx.x;
    if (i < n4) {
        float4 v = reinterpret_cast<const float4*>(in)[i];
        v.x = wmma::__float_to_tf32(v.x); v.y = wmma::__float_to_tf32(v.y);
        v.z = wmma::__float_to_tf32(v.z); v.w = wmma::__float_to_tf32(v.w);
        reinterpret_cast<float4*>(out)[i] = v;
    }
}

// ================= TF32 GEMM, cp.async 2-stage: C[M,N] = A @ W^T =================
// A, W already tf32-rounded. BM=BN=128, BK=32, 256 thr, warp tile 32x64.
__device__ __forceinline__ void gemm_core(
    const float* __restrict__ A, const float* __restrict__ W,
    float* __restrict__ C, int N, int K, int m0, int n0) {
    extern __shared__ float sm[];
    float* As = sm;                   // 2 * 128 * LDA
    float* Ws = sm + 2 * BM * LDA;    // 2 * 128 * LDA
    const int tid = threadIdx.x;
    const int warp = tid >> 5;
    const int wm = warp >> 1;   // 0..3 : 32-row strip
    const int wn = warp & 1;    // 0..1 : 64-col strip

    wmma::fragment<wmma::accumulator, 16, 16, 8, float> acc[2][4];
#pragma unroll
    for (int i = 0; i < 2; i++)
#pragma unroll
        for (int j = 0; j < 4; j++) wmma::fill_fragment(acc[i][j], 0.f);

    const float* Ab = A + (size_t)m0 * K;
    const float* Wb = W + (size_t)n0 * K;

#define LOAD_SLAB(it, buf)                                                      \
    {                                                                           \
        const int k0 = (it) << 5;                                               \
        float* ad = As + (buf) * BM * LDA;                                      \
        float* wd = Ws + (buf) * BN * LDA;                                      \
        _Pragma("unroll")                                                       \
        for (int i = 0; i < 4; i++) {                                           \
            int ch = tid + i * 256;                                             \
            int r = ch >> 3, c4 = (ch & 7) << 2;                                \
            cp16(ad + r * LDA + c4, Ab + (size_t)r * K + k0 + c4);              \
            cp16(wd + r * LDA + c4, Wb + (size_t)r * K + k0 + c4);              \
        }                                                                       \
    }

    const int nIter = K >> 5;
    LOAD_SLAB(0, 0); CP_COMMIT();
    for (int it = 0; it < nIter; ++it) {
        const int buf = it & 1;
        if (it + 1 < nIter) { LOAD_SLAB(it + 1, buf ^ 1); CP_COMMIT(); CP_WAIT1(); }
        else CP_WAIT0();
        __syncthreads();
        const float* as = As + buf * BM * LDA;
        const float* ws = Ws + buf * BN * LDA;
#pragma unroll
        for (int kk = 0; kk < 32; kk += 8) {
            wmma::fragment<wmma::matrix_a, 16, 16, 8, wmma::precision::tf32, wmma::row_major> a[2];
            wmma::fragment<wmma::matrix_b, 16, 16, 8, wmma::precision::tf32, wmma::col_major> b[4];
#pragma unroll
            for (int i = 0; i < 2; i++)
                wmma::load_matrix_sync(a[i], &as[(wm * 32 + i * 16) * LDA + kk], LDA);
#pragma unroll
            for (int j = 0; j < 4; j++)
                wmma::load_matrix_sync(b[j], &ws[(wn * 64 + j * 16) * LDA + kk], LDA);
#pragma unroll
            for (int i = 0; i < 2; i++)
#pragma unroll
                for (int j = 0; j < 4; j++)
                    wmma::mma_sync(acc[i][j], a[i], b[j], acc[i][j]);
        }
        __syncthreads();
    }
#undef LOAD_SLAB
#pragma unroll
    for (int i = 0; i < 2; i++)
#pragma unroll
        for (int j = 0; j < 4; j++)
            wmma::store_matrix_sync(&C[(size_t)(m0 + wm * 32 + i * 16) * N + n0 + wn * 64 + j * 16],
                                    acc[i][j], N, wmma::mem_row_major);
}

__global__ __launch_bounds__(256, 2) void gemm_proj(
    const float* __restrict__ A, const float* __restrict__ W, float* __restrict__ C, int K) {
    gemm_core(A, W, C, Ecfg, K, blockIdx.y * BM, blockIdx.x * BN);
}

// fused QKV: 12 n-tiles = 8 (Q, N=1024) + 2 (K, N=256) + 2 (V, N=256)
__global__ __launch_bounds__(256, 2) void gemm_qkv(
    const float* __restrict__ x,
    const float* __restrict__ Wq, const float* __restrict__ Wk, const float* __restrict__ Wv,
    float* __restrict__ Cq, float* __restrict__ Ck, float* __restrict__ Cv, int K) {
    const int ng = blockIdx.x * BN;
    const float* W; float* C; int N, n0;
    if (ng < 1024)      { W = Wq; C = Cq; N = 1024; n0 = ng; }
    else if (ng < 1280) { W = Wk; C = Ck; N = 256;  n0 = ng - 1024; }
    else                { W = Wv; C = Cv; N = 256;  n0 = ng - 1280; }
    gemm_core(x, W, C, N, K, blockIdx.y * BM, n0);
}

// ---------------- rope + rmsnorm for Q (writes tf32-rounded) ----------------
__global__ void rope_rms_kernel(const float* __restrict__ raw,
                                const float* __restrict__ cosb,
                                const float* __restrict__ sinb,
                                float* __restrict__ dst, int T) {
    const int warp = threadIdx.x >> 5, lane = threadIdx.x & 31;
    const int t = blockIdx.x * 8 + warp;
    const int h = blockIdx.y, b = blockIdx.z;
    const int NH = gridDim.y;
    const float* src = raw + (((size_t)b * T + t) * NH + h) * 64;
    float x1 = src[lane], x2 = src[32 + lane];
    float c = cosb[(size_t)t * 32 + lane];
    float s = sinb[(size_t)t * 32 + lane];
    float r1 = x1 * c + x2 * s;
    float r2 = x2 * c - x1 * s;
    float ss = r1 * r1 + r2 * r2;
#pragma unroll
    for (int o = 16; o; o >>= 1) ss += __shfl_xor_sync(0xffffffffu, ss, o);
    float inv = rsqrtf(ss * (1.f / 64.f) + 1.1920929e-07f);
    float* d = dst + (((size_t)b * NH + h) * T + t) * 64;
    d[lane] = wmma::__float_to_tf32(r1 * inv);
    d[32 + lane] = wmma::__float_to_tf32(r2 * inv);
}

// ---------------- fused K rope+rms AND V gate (writes tf32-rounded) ----------------
__global__ void kv_post_kernel(const float* __restrict__ kraw,
                               const float* __restrict__ vraw,
                               const float* __restrict__ x,
                               const float* __restrict__ ve,
                               const float* __restrict__ cosb,
                               const float* __restrict__ sinb,
                               const float* __restrict__ Wgate,
                               float* __restrict__ k_t,
                               float* __restrict__ v_t, int T) {
    const int warp = threadIdx.x >> 5, lane = threadIdx.x & 31;
    const int t = blockIdx.x * 8 + warp;
    const int h = blockIdx.y, b = blockIdx.z;
    const size_t tok = (size_t)b * T + t;
    {
        const float* src = kraw + (tok * HKV + h) * 64;
        float x1 = src[lane], x2 = src[32 + lane];
        float c = cosb[(size_t)t * 32 + lane];
        float s = sinb[(size_t)t * 32 + lane];
        float r1 = x1 * c + x2 * s;
        float r2 = x2 * c - x1 * s;
        float ss = r1 * r1 + r2 * r2;
#pragma unroll
        for (int o = 16; o; o >>= 1) ss += __shfl_xor_sync(0xffffffffu, ss, o);
        float inv = rsqrtf(ss * (1.f / 64.f) + 1.1920929e-07f);
        float* d = k_t + (((size_t)b * HKV + h) * T + t) * 64;
        d[lane] = wmma::__float_to_tf32(r1 * inv);
        d[32 + lane] = wmma::__float_to_tf32(r2 * inv);
    }
    {
        float g = x[tok * Ecfg + lane] * Wgate[h * 32 + lane];
#pragma unroll
        for (int o = 16; o; o >>= 1) g += __shfl_xor_sync(0xffffffffu, g, o);
        float gate = 2.f / (1.f + __expf(-g));
        const float* vs = vraw + (tok * HKV + h) * 64;
        const float* ves = ve + (tok * HKV + h) * 64;
        float* d = v_t + (((size_t)b * HKV + h) * T + t) * 64;
        d[lane] = wmma::__float_to_tf32(vs[lane] + gate * ves[lane]);
        d[32 + lane] = wmma::__float_to_tf32(vs[32 + lane] + gate * ves[32 + lane]);
    }
}

// ================ sliding-window flash attention: Q-tile 128, cp.async K/V ================
// q,k,v are tf32-pre-rounded. Fixed-max softmax (scores <= 8 by Cauchy-Schwarz
// after rmsnorm), O persists in accumulator fragments. Output tf32-rounded.
__global__ __launch_bounds__(256, 2) void attn_tc(
    const float* __restrict__ q, const float* __restrict__ k,
    const float* __restrict__ v, float* __restrict__ out,
    const int* __restrict__ wptr, int T) {
    extern __shared__ float sm[];
    float* Ks = sm;                    // 2 * 64 * LDK
    float* Vs = sm + 2 * 64 * LDK;     // 2 * 64 * LDK
    float* Ss = sm + 4 * 64 * LDK;     // 128 * LDK

    const int qtile = blockIdx.x, h = blockIdx.y, b = blockIdx.z;
    const int W = wptr[0];
    const int tid = threadIdx.x;
    const int warp = tid >> 5;               // 0..7, 16-row strip each
    const int row = tid >> 1, half = tid & 1;
    const int qbase = qtile * 128;
    const int qrow = qbase + row;

    // persistent Q fragments (scale 1/8 exact on pre-rounded values)
    wmma::fragment<wmma::matrix_a, 16, 16, 8, wmma::precision::tf32, wmma::row_major> qf[8];
    {
        const float* qptr = q + ((size_t)(b * Hh + h) * T + qbase + warp * 16) * Dd;
#pragma unroll
        for (int kk = 0; kk < 8; kk++) {
            wmma::load_matrix_sync(qf[kk], qptr + kk * 8, Dd);
#pragma unroll
            for (int e = 0; e < qf[kk].num_elements; e++)
                qf[kk].x[e] *= 0.125f;
        }
    }
    wmma::fragment<wmma::accumulator, 16, 16, 8, float> oa[4];
#pragma unroll
    for (int j = 0; j < 4; j++) wmma::fill_fragment(oa[j], 0.f);

    const int hkv = h >> 2;
    const float* kb = k + (size_t)(b * HKV + hkv) * T * Dd;
    const float* vb = v + (size_t)(b * HKV + hkv) * T * Dd;
    int kmin = qbase - W; if (kmin < 0) kmin = 0;
    const int t0 = kmin >> 6;
    const int ktend = (qbase + 127) >> 6;

#define LOAD_KV(kt, buf)                                                        \
    {                                                                           \
        const float* kp = kb + (size_t)(kt) * 64 * Dd;                          \
        const float* vp = vb + (size_t)(kt) * 64 * Dd;                          \
        float* kd = Ks + (buf) * 64 * LDK;                                      \
        float* vd = Vs + (buf) * 64 * LDK;                                      \
        _Pragma("unroll")                                                       \
        for (int i = 0; i < 4; i++) {                                           \
            int ch = tid + i * 256;                                             \
            int r = ch >> 4, c4 = (ch & 15) << 2;                               \
            cp16(kd + r * LDK + c4, kp + r * 64 + c4);                          \
            cp16(vd + r * LDK + c4, vp + r * 64 + c4);                          \
        }                                                                       \
    }

    LOAD_KV(t0, 0); CP_COMMIT();
    float l_run = 0.f;

    for (int kt = t0; kt <= ktend; ++kt) {
        const int buf = (kt - t0) & 1;
        if (kt < ktend) { LOAD_KV(kt + 1, buf ^ 1); CP_COMMIT(); CP_WAIT1(); }
        else CP_WAIT0();
        __syncthreads();
        const float* ks = Ks + buf * 64 * LDK;
        const float* vs = Vs + buf * 64 * LDK;

        // S = Q @ K^T (warp strip 16x64)
        {
            wmma::fragment<wmma::accumulator, 16, 16, 8, float> sa[4];
#pragma unroll
            for (int j = 0; j < 4; j++) wmma::fill_fragment(sa[j], 0.f);
#pragma unroll
            for (int kk = 0; kk < 8; kk++) {
#pragma unroll
                for (int j = 0; j < 4; j++) {
                    wmma::fragment<wmma::matrix_b, 16, 16, 8, wmma::precision::tf32, wmma::col_major> bf;
                    wmma::load_matrix_sync(bf, &ks[(j * 16) * LDK + kk * 8], LDK);
                    wmma::mma_sync(sa[j], qf[kk], bf, sa[j]);
                }
            }
#pragma unroll
            for (int j = 0; j < 4; j++)
                wmma::store_matrix_sync(&Ss[(warp * 16) * LDK + j * 16], sa[j], LDK, wmma::mem_row_major);
        }
        __syncwarp();

        // fixed-max softmax: p = exp(s - 8), window mask
        {
            float* srow = &Ss[row * LDK + half * 32];
            float lloc = 0.f;
#pragma unroll
            for (int c = 0; c < 32; c++) {
                int col = (kt << 6) + (half << 5) + c;
                float p = 0.f;
                if (col <= qrow && col >= qrow - W) {
                    p = __expf(srow[c] - 8.f);
                    lloc += p;
                }
                srow[c] = wmma::__float_to_tf32(p);
            }
            l_run += lloc;
        }
        __syncwarp();

        // O += P @ V
#pragma unroll
        for (int kk = 0; kk < 8; kk++) {
            wmma::fragment<wmma::matrix_a, 16, 16, 8, wmma::precision::tf32, wmma::row_major> pf;
            wmma::load_matrix_sync(pf, &Ss[(warp * 16) * LDK + kk * 8], LDK);
#pragma unroll
            for (int j = 0; j < 4; j++) {
                wmma::fragment<wmma::matrix_b, 16, 16, 8, wmma::precision::tf32, wmma::row_major> bf;
                wmma::load_matrix_sync(bf, &vs[(kk * 8) * LDK + j * 16], LDK);
                wmma::mma_sync(oa[j], pf, bf, oa[j]);
            }
        }
        __syncthreads();
    }
#undef LOAD_KV

    // epilogue: stage O, normalize, write tf32-rounded [B,T,H,D]
#pragma unroll
    for (int j = 0; j < 4; j++)
        wmma::store_matrix_sync(&Ss[(warp * 16) * LDK + j * 16], oa[j], LDK, wmma::mem_row_major);
    __syncwarp();
    {
        float l_tot = l_run + __shfl_xor_sync(0xffffffffu, l_run, 1);
        float inv = 1.f / l_tot;
        float* op = out + ((size_t)(b * T + qrow) * Hh + h) * Dd + half * 32;
        const float* orow = &Ss[row * LDK + half * 32];
#pragma unroll
        for (int c = 0; c < 32; c += 4) {
            float4 o = make_float4(wmma::__float_to_tf32(orow[c] * inv),
                                   wmma::__float_to_tf32(orow[c + 1] * inv),
                                   wmma::__float_to_tf32(orow[c + 2] * inv),
                                   wmma::__float_to_tf32(orow[c + 3] * inv));
            *reinterpret_cast<float4*>(&op[c]) = o;
        }
    }
}

// ---------------- launch ----------------
extern "C" void kernel_launch(void* const* d_in, const int* in_sizes, int n_in,
                              void* d_out, int out_size) {
    const float* x     = (const float*)d_in[0];
    const float* ve    = (const float*)d_in[1];
    const float* cosb  = (const float*)d_in[2];
    const float* sinb  = (const float*)d_in[3];
    const float* Wq    = (const float*)d_in[4];
    const float* Wk    = (const float*)d_in[5];
    const float* Wv    = (const float*)d_in[6];
    const float* Wproj = (const float*)d_in[7];
    const float* Wgate = (const float*)d_in[8];
    const int*   wsz   = (const int*)d_in[9];

    int T = in_sizes[2] / 32;
    int B = in_sizes[0] / (T * Ecfg);
    int M = B * T;

    float *qraw, *kraw, *vraw, *qt, *kt, *vt, *attn;
    float *xtf, *wqt, *wkt, *wvt, *wpt;
    cudaGetSymbolAddress((void**)&qraw, g_qraw);
    cudaGetSymbolAddress((void**)&kraw, g_kraw);
    cudaGetSymbolAddress((void**)&vraw, g_vraw);
    cudaGetSymbolAddress((void**)&qt,   g_qt);
    cudaGetSymbolAddress((void**)&kt,   g_kt);
    cudaGetSymbolAddress((void**)&vt,   g_vt);
    cudaGetSymbolAddress((void**)&attn, g_attn);
    cudaGetSymbolAddress((void**)&xtf,  g_xtf);
    cudaGetSymbolAddress((void**)&wqt,  g_wqt);
    cudaGetSymbolAddress((void**)&wkt,  g_wkt);
    cudaGetSymbolAddress((void**)&wvt,  g_wvt);
    cudaGetSymbolAddress((void**)&wpt,  g_wpt);

    const int gemm_smem = 2 * (BM + BN) * LDA * 4;          // 81920
    const int attn_smem = (4 * 64 * LDK + 128 * LDK) * 4;   // 110592
    cudaFuncSetAttribute(gemm_qkv, cudaFuncAttributeMaxDynamicSharedMemorySize, gemm_smem);
    cudaFuncSetAttribute(gemm_proj, cudaFuncAttributeMaxDynamicSharedMemorySize, gemm_smem);
    cudaFuncSetAttribute(attn_tc, cudaFuncAttributeMaxDynamicSharedMemorySize, attn_smem);

    // tf32 pre-round: x + weights
    {
        int n4;
        n4 = M * Ecfg / 4;        cvt_tf32<<<(n4 + 255) / 256, 256>>>(x, xtf, n4);
        n4 = Ecfg * Ecfg / 4;     cvt_tf32<<<(n4 + 255) / 256, 256>>>(Wq, wqt, n4);
        n4 = 256 * Ecfg / 4;      cvt_tf32<<<(n4 + 255) / 256, 256>>>(Wk, wkt, n4);
        n4 = 256 * Ecfg / 4;      cvt_tf32<<<(n4 + 255) / 256, 256>>>(Wv, wvt, n4);
        n4 = Ecfg * Ecfg / 4;     cvt_tf32<<<(n4 + 255) / 256, 256>>>(Wproj, wpt, n4);
    }

    gemm_qkv<<<dim3(1536 / BN, M / BM), 256, gemm_smem>>>(xtf, wqt, wkt, wvt, qraw, kraw, vraw, Ecfg);

    rope_rms_kernel<<<dim3(T / 8, Hh, B), 256>>>(qraw, cosb, sinb, qt, T);
    kv_post_kernel <<<dim3(T / 8, HKV, B), 256>>>(kraw, vraw, x, ve, cosb, sinb, Wgate, kt, vt, T);

    attn_tc<<<dim3(T / 128, Hh, B), 256, attn_smem>>>(qt, kt, vt, attn, wsz, T);

    gemm_proj<<<dim3(Ecfg / BN, M / BM), 256, gemm_smem>>>(attn, wpt, (float*)d_out, Ecfg);
}

// round 5
// speedup vs baseline: 1.0079x; 1.0079x over previous
#include <cuda_runtime.h>
#include <mma.h>
#include <cstdint>

using namespace nvcuda;

#define Ecfg 1024
#define Hh   16
#define HKV  4
#define Dd   64

#define BM  128
#define BN  64
#define LDA 40
#define LDK 72

// ---------------- scratch (device globals) ----------------
__device__ float g_qraw[2 * 2048 * 1024];
__device__ float g_kraw[2 * 2048 * 256];
__device__ float g_vraw[2 * 2048 * 256];
__device__ float g_qt  [2 * 16 * 2048 * 64];
__device__ float g_kt  [2 * 4  * 2048 * 64];
__device__ float g_vt  [2 * 4  * 2048 * 64];
__device__ float g_attn[2 * 2048 * 1024];
__device__ float g_xtf [2 * 2048 * 1024];
__device__ float g_wqt [1024 * 1024];
__device__ float g_wkt [256 * 1024];
__device__ float g_wvt [256 * 1024];
__device__ float g_wpt [1024 * 1024];

// ---------------- cp.async helpers ----------------
__device__ __forceinline__ void cp16(float* smem_dst, const float* gsrc) {
    uint32_t s = (uint32_t)__cvta_generic_to_shared(smem_dst);
    asm volatile("cp.async.cg.shared.global [%0], [%1], 16;\n" :: "r"(s), "l"(gsrc));
}
#define CP_COMMIT() asm volatile("cp.async.commit_group;\n" ::: "memory")
#define CP_WAIT1()  asm volatile("cp.async.wait_group 1;\n" ::: "memory")
#define CP_WAIT0()  asm volatile("cp.async.wait_group 0;\n" ::: "memory")

// ---------------- fused tf32 pre-round of x + all weights (1 launch) ----------------
#define N4_WQ 262144
#define N4_WK 65536
#define N4_WV 65536
#define N4_WP 262144
__global__ void cvt_all(const float* __restrict__ x,  const float* __restrict__ wq,
                        const float* __restrict__ wk, const float* __restrict__ wv,
                        const float* __restrict__ wp,
                        float* __restrict__ xo, float* __restrict__ wqo,
                        float* __restrict__ wko, float* __restrict__ wvo,
                        float* __restrict__ wpo, int n4x) {
    int i = blockIdx.x * blockDim.x + threadIdx.x;
    const float4* s; float4* d; int j;
    if (i < n4x) { s = (const float4*)x; d = (float4*)xo; j = i; }
    else {
        i -= n4x;
        if (i < N4_WQ)                          { s = (const float4*)wq; d = (float4*)wqo; j = i; }
        else if (i < N4_WQ + N4_WK)             { s = (const float4*)wk; d = (float4*)wko; j = i - N4_WQ; }
        else if (i < N4_WQ + N4_WK + N4_WV)     { s = (const float4*)wv; d = (float4*)wvo; j = i - N4_WQ - N4_WK; }
        else if (i < N4_WQ + N4_WK + N4_WV + N4_WP) { s = (const float4*)wp; d = (float4*)wpo; j = i - N4_WQ - N4_WK - N4_WV; }
        else return;
    }
    float4 v = s[j];
    v.x = wmma::__float_to_tf32(v.x); v.y = wmma::__float_to_tf32(v.y);
    v.z = wmma::__float_to_tf32(v.z); v.w = wmma::__float_to_tf32(v.w);
    d[j] = v;
}

// ================= TF32 GEMM, cp.async 2-stage: C[M,N] = A @ W^T =================
// BM=128, BN=64, BK=32, 256 thr = 8 warps (4M x 2N), warp tile 32x32.
// 3 blocks/SM -> gemm_qkv's 384 blocks run in one full wave.
__device__ __forceinline__ void gemm_core(
    const float* __restrict__ A, const float* __restrict__ W,
    float* __restrict__ C, int N, int K, int m0, int n0) {
    extern __shared__ float sm[];
    float* As = sm;                   // 2 * 128 * LDA
    float* Ws = sm + 2 * BM * LDA;    // 2 * 64 * LDA
    const int tid = threadIdx.x;
    const int warp = tid >> 5;
    const int wm = warp >> 1;   // 0..3
    const int wn = warp & 1;    // 0..1

    wmma::fragment<wmma::accumulator, 16, 16, 8, float> acc[2][2];
#pragma unroll
    for (int i = 0; i < 2; i++)
#pragma unroll
        for (int j = 0; j < 2; j++) wmma::fill_fragment(acc[i][j], 0.f);

    const float* Ab = A + (size_t)m0 * K;
    const float* Wb = W + (size_t)n0 * K;

#define LOAD_SLAB(it, buf)                                                      \
    {                                                                           \
        const int k0 = (it) << 5;                                               \
        float* ad = As + (buf) * BM * LDA;                                      \
        float* wd = Ws + (buf) * BN * LDA;                                      \
        _Pragma("unroll")                                                       \
        for (int i = 0; i < 4; i++) {                                           \
            int ch = tid + i * 256;                                             \
            int r = ch >> 3, c4 = (ch & 7) << 2;                                \
            cp16(ad + r * LDA + c4, Ab + (size_t)r * K + k0 + c4);              \
        }                                                                       \
        _Pragma("unroll")                                                       \
        for (int i = 0; i < 2; i++) {                                           \
            int ch = tid + i * 256;                                             \
            int r = ch >> 3, c4 = (ch & 7) << 2;                                \
            cp16(wd + r * LDA + c4, Wb + (size_t)r * K + k0 + c4);              \
        }                                                                       \
    }

    const int nIter = K >> 5;
    LOAD_SLAB(0, 0); CP_COMMIT();
    for (int it = 0; it < nIter; ++it) {
        const int buf = it & 1;
        if (it + 1 < nIter) { LOAD_SLAB(it + 1, buf ^ 1); CP_COMMIT(); CP_WAIT1(); }
        else CP_WAIT0();
        __syncthreads();
        const float* as = As + buf * BM * LDA;
        const float* ws = Ws + buf * BN * LDA;
#pragma unroll
        for (int kk = 0; kk < 32; kk += 8) {
            wmma::fragment<wmma::matrix_a, 16, 16, 8, wmma::precision::tf32, wmma::row_major> a[2];
            wmma::fragment<wmma::matrix_b, 16, 16, 8, wmma::precision::tf32, wmma::col_major> b[2];
#pragma unroll
            for (int i = 0; i < 2; i++)
                wmma::load_matrix_sync(a[i], &as[(wm * 32 + i * 16) * LDA + kk], LDA);
#pragma unroll
            for (int j = 0; j < 2; j++)
                wmma::load_matrix_sync(b[j], &ws[(wn * 32 + j * 16) * LDA + kk], LDA);
#pragma unroll
            for (int i = 0; i < 2; i++)
#pragma unroll
                for (int j = 0; j < 2; j++)
                    wmma::mma_sync(acc[i][j], a[i], b[j], acc[i][j]);
        }
        __syncthreads();
    }
#undef LOAD_SLAB
#pragma unroll
    for (int i = 0; i < 2; i++)
#pragma unroll
        for (int j = 0; j < 2; j++)
            wmma::store_matrix_sync(&C[(size_t)(m0 + wm * 32 + i * 16) * N + n0 + wn * 32 + j * 16],
                                    acc[i][j], N, wmma::mem_row_major);
}

__global__ __launch_bounds__(256, 3) void gemm_proj(
    const float* __restrict__ A, const float* __restrict__ W, float* __restrict__ C, int K) {
    gemm_core(A, W, C, Ecfg, K, blockIdx.y * BM, blockIdx.x * BN);
}

// fused QKV: 24 n-tiles = 16 (Q, N=1024) + 4 (K, N=256) + 4 (V, N=256)
__global__ __launch_bounds__(256, 3) void gemm_qkv(
    const float* __restrict__ x,
    const float* __restrict__ Wq, const float* __restrict__ Wk, const float* __restrict__ Wv,
    float* __restrict__ Cq, float* __restrict__ Ck, float* __restrict__ Cv, int K) {
    const int ng = blockIdx.x * BN;
    const float* W; float* C; int N, n0;
    if (ng < 1024)      { W = Wq; C = Cq; N = 1024; n0 = ng; }
    else if (ng < 1280) { W = Wk; C = Ck; N = 256;  n0 = ng - 1024; }
    else                { W = Wv; C = Cv; N = 256;  n0 = ng - 1280; }
    gemm_core(x, W, C, N, K, blockIdx.y * BM, n0);
}

// ---------------- rope + rmsnorm for Q (writes tf32-rounded) ----------------
__global__ void rope_rms_kernel(const float* __restrict__ raw,
                                const float* __restrict__ cosb,
                                const float* __restrict__ sinb,
                                float* __restrict__ dst, int T) {
    const int warp = threadIdx.x >> 5, lane = threadIdx.x & 31;
    const int t = blockIdx.x * 8 + warp;
    const int h = blockIdx.y, b = blockIdx.z;
    const int NH = gridDim.y;
    const float* src = raw + (((size_t)b * T + t) * NH + h) * 64;
    float x1 = src[lane], x2 = src[32 + lane];
    float c = cosb[(size_t)t * 32 + lane];
    float s = sinb[(size_t)t * 32 + lane];
    float r1 = x1 * c + x2 * s;
    float r2 = x2 * c - x1 * s;
    float ss = r1 * r1 + r2 * r2;
#pragma unroll
    for (int o = 16; o; o >>= 1) ss += __shfl_xor_sync(0xffffffffu, ss, o);
    float inv = rsqrtf(ss * (1.f / 64.f) + 1.1920929e-07f);
    float* d = dst + (((size_t)b * NH + h) * T + t) * 64;
    d[lane] = wmma::__float_to_tf32(r1 * inv);
    d[32 + lane] = wmma::__float_to_tf32(r2 * inv);
}

// ---------------- fused K rope+rms AND V gate (writes tf32-rounded) ----------------
__global__ void kv_post_kernel(const float* __restrict__ kraw,
                               const float* __restrict__ vraw,
                               const float* __restrict__ x,
                               const float* __restrict__ ve,
                               const float* __restrict__ cosb,
                               const float* __restrict__ sinb,
                               const float* __restrict__ Wgate,
                               float* __restrict__ k_t,
                               float* __restrict__ v_t, int T) {
    const int warp = threadIdx.x >> 5, lane = threadIdx.x & 31;
    const int t = blockIdx.x * 8 + warp;
    const int h = blockIdx.y, b = blockIdx.z;
    const size_t tok = (size_t)b * T + t;
    {
        const float* src = kraw + (tok * HKV + h) * 64;
        float x1 = src[lane], x2 = src[32 + lane];
        float c = cosb[(size_t)t * 32 + lane];
        float s = sinb[(size_t)t * 32 + lane];
        float r1 = x1 * c + x2 * s;
        float r2 = x2 * c - x1 * s;
        float ss = r1 * r1 + r2 * r2;
#pragma unroll
        for (int o = 16; o; o >>= 1) ss += __shfl_xor_sync(0xffffffffu, ss, o);
        float inv = rsqrtf(ss * (1.f / 64.f) + 1.1920929e-07f);
        float* d = k_t + (((size_t)b * HKV + h) * T + t) * 64;
        d[lane] = wmma::__float_to_tf32(r1 * inv);
        d[32 + lane] = wmma::__float_to_tf32(r2 * inv);
    }
    {
        float g = x[tok * Ecfg + lane] * Wgate[h * 32 + lane];
#pragma unroll
        for (int o = 16; o; o >>= 1) g += __shfl_xor_sync(0xffffffffu, g, o);
        float gate = 2.f / (1.f + __expf(-g));
        const float* vs = vraw + (tok * HKV + h) * 64;
        const float* ves = ve + (tok * HKV + h) * 64;
        float* d = v_t + (((size_t)b * HKV + h) * T + t) * 64;
        d[lane] = wmma::__float_to_tf32(vs[lane] + gate * ves[lane]);
        d[32 + lane] = wmma::__float_to_tf32(vs[32 + lane] + gate * ves[32 + lane]);
    }
}

// ================ sliding-window flash attention, GQA-fused ================
// One block = 64-query tile x 2 query heads sharing one KV head's K/V tiles.
// 256 thr = 8 warps: warps 0-3 -> head A (16-row strips), warps 4-7 -> head B.
// K/V double-buffered via cp.async; fixed-max softmax (scores <= 8 after
// rmsnorm + 1/8 scale); O persists in accumulator fragments.
__global__ __launch_bounds__(256, 2) void attn_tc(
    const float* __restrict__ q, const float* __restrict__ k,
    const float* __restrict__ v, float* __restrict__ out,
    const int* __restrict__ wptr, int T) {
    extern __shared__ float sm[];
    float* Ks = sm;                    // 2 * 64 * LDK
    float* Vs = sm + 2 * 64 * LDK;     // 2 * 64 * LDK
    float* Ss = sm + 4 * 64 * LDK;     // 128 * LDK (8 warp strips)

    const int qtile = blockIdx.x, hg = blockIdx.y, b = blockIdx.z;
    const int hkv = hg >> 1;
    const int hbase = hkv * 4 + (hg & 1) * 2;
    const int W = wptr[0];
    const int tid = threadIdx.x;
    const int warp = tid >> 5, lane = tid & 31;
    const int h = hbase + (warp >> 2);          // this warp's query head
    const int qbase = qtile * 64;
    const int qrow = qbase + (warp & 3) * 16 + (lane >> 1);
    const int half = lane & 1;
    const int sRow = warp * 16 + (lane >> 1);   // row in Ss

    // persistent Q fragments (tf32 pre-rounded; *0.125 is exact)
    wmma::fragment<wmma::matrix_a, 16, 16, 8, wmma::precision::tf32, wmma::row_major> qf[8];
    {
        const float* qptr = q + ((size_t)(b * Hh + h) * T + qbase + (warp & 3) * 16) * Dd;
#pragma unroll
        for (int kk = 0; kk < 8; kk++) {
            wmma::load_matrix_sync(qf[kk], qptr + kk * 8, Dd);
#pragma unroll
            for (int e = 0; e < qf[kk].num_elements; e++)
                qf[kk].x[e] *= 0.125f;
        }
    }
    wmma::fragment<wmma::accumulator, 16, 16, 8, float> oa[4];
#pragma unroll
    for (int j = 0; j < 4; j++) wmma::fill_fragment(oa[j], 0.f);

    const float* kb = k + (size_t)(b * HKV + hkv) * T * Dd;
    const float* vb = v + (size_t)(b * HKV + hkv) * T * Dd;
    int kmin = qbase - W; if (kmin < 0) kmin = 0;
    const int t0 = kmin >> 6;

#define LOAD_KV(kt, buf)                                                        \
    {                                                                           \
        const float* kp = kb + (size_t)(kt) * 64 * Dd;                          \
        const float* vp = vb + (size_t)(kt) * 64 * Dd;                          \
        float* kd = Ks + (buf) * 64 * LDK;                                      \
        float* vd = Vs + (buf) * 64 * LDK;                                      \
        _Pragma("unroll")                                                       \
        for (int i = 0; i < 4; i++) {                                           \
            int ch = tid + i * 256;                                             \
            int r = ch >> 4, c4 = (ch & 15) << 2;                               \
            cp16(kd + r * LDK + c4, kp + r * 64 + c4);                          \
            cp16(vd + r * LDK + c4, vp + r * 64 + c4);                          \
        }                                                                       \
    }

    LOAD_KV(t0, 0); CP_COMMIT();
    float l_run = 0.f;

    for (int kt = t0; kt <= qtile; ++kt) {
        const int buf = (kt - t0) & 1;
        if (kt < qtile) { LOAD_KV(kt + 1, buf ^ 1); CP_COMMIT(); CP_WAIT1(); }
        else CP_WAIT0();
        __syncthreads();
        const float* ks = Ks + buf * 64 * LDK;
        const float* vs = Vs + buf * 64 * LDK;

        // S = Q @ K^T (warp strip 16x64)
        {
            wmma::fragment<wmma::accumulator, 16, 16, 8, float> sa[4];
#pragma unroll
            for (int j = 0; j < 4; j++) wmma::fill_fragment(sa[j], 0.f);
#pragma unroll
            for (int kk = 0; kk < 8; kk++) {
#pragma unroll
                for (int j = 0; j < 4; j++) {
                    wmma::fragment<wmma::matrix_b, 16, 16, 8, wmma::precision::tf32, wmma::col_major> bf;
                    wmma::load_matrix_sync(bf, &ks[(j * 16) * LDK + kk * 8], LDK);
                    wmma::mma_sync(sa[j], qf[kk], bf, sa[j]);
                }
            }
#pragma unroll
            for (int j = 0; j < 4; j++)
                wmma::store_matrix_sync(&Ss[(warp * 16) * LDK + j * 16], sa[j], LDK, wmma::mem_row_major);
        }
        __syncwarp();

        // fixed-max softmax: p = exp(s - 8), window mask (own half-row)
        {
            float* srow = &Ss[sRow * LDK + half * 32];
            float lloc = 0.f;
#pragma unroll
            for (int c = 0; c < 32; c++) {
                int col = (kt << 6) + (half << 5) + c;
                float p = 0.f;
                if (col <= qrow && col >= qrow - W) {
                    p = __expf(srow[c] - 8.f);
                    lloc += p;
                }
                srow[c] = wmma::__float_to_tf32(p);
            }
            l_run += lloc;
        }
        __syncwarp();

        // O += P @ V (own strip)
#pragma unroll
        for (int kk = 0; kk < 8; kk++) {
            wmma::fragment<wmma::matrix_a, 16, 16, 8, wmma::precision::tf32, wmma::row_major> pf;
            wmma::load_matrix_sync(pf, &Ss[(warp * 16) * LDK + kk * 8], LDK);
#pragma unroll
            for (int j = 0; j < 4; j++) {
                wmma::fragment<wmma::matrix_b, 16, 16, 8, wmma::precision::tf32, wmma::row_major> bf;
                wmma::load_matrix_sync(bf, &vs[(kk * 8) * LDK + j * 16], LDK);
                wmma::mma_sync(oa[j], pf, bf, oa[j]);
            }
        }
        __syncthreads();
    }
#undef LOAD_KV

    // epilogue: stage O in own strip, normalize, write tf32-rounded [B,T,H,D]
#pragma unroll
    for (int j = 0; j < 4; j++)
        wmma::store_matrix_sync(&Ss[(warp * 16) * LDK + j * 16], oa[j], LDK, wmma::mem_row_major);
    __syncwarp();
    {
        float l_tot = l_run + __shfl_xor_sync(0xffffffffu, l_run, 1);
        float inv = 1.f / l_tot;
        float* op = out + ((size_t)(b * T + qrow) * Hh + h) * Dd + half * 32;
        const float* orow = &Ss[sRow * LDK + half * 32];
#pragma unroll
        for (int c = 0; c < 32; c += 4) {
            float4 o = make_float4(wmma::__float_to_tf32(orow[c] * inv),
                                   wmma::__float_to_tf32(orow[c + 1] * inv),
                                   wmma::__float_to_tf32(orow[c + 2] * inv),
                                   wmma::__float_to_tf32(orow[c + 3] * inv));
            *reinterpret_cast<float4*>(&op[c]) = o;
        }
    }
}

// ---------------- launch ----------------
extern "C" void kernel_launch(void* const* d_in, const int* in_sizes, int n_in,
                              void* d_out, int out_size) {
    const float* x     = (const float*)d_in[0];
    const float* ve    = (const float*)d_in[1];
    const float* cosb  = (const float*)d_in[2];
    const float* sinb  = (const float*)d_in[3];
    const float* Wq    = (const float*)d_in[4];
    const float* Wk    = (const float*)d_in[5];
    const float* Wv    = (const float*)d_in[6];
    const float* Wproj = (const float*)d_in[7];
    const float* Wgate = (const float*)d_in[8];
    const int*   wsz   = (const int*)d_in[9];

    int T = in_sizes[2] / 32;
    int B = in_sizes[0] / (T * Ecfg);
    int M = B * T;

    float *qraw, *kraw, *vraw, *qt, *kt, *vt, *attn;
    float *xtf, *wqt, *wkt, *wvt, *wpt;
    cudaGetSymbolAddress((void**)&qraw, g_qraw);
    cudaGetSymbolAddress((void**)&kraw, g_kraw);
    cudaGetSymbolAddress((void**)&vraw, g_vraw);
    cudaGetSymbolAddress((void**)&qt,   g_qt);
    cudaGetSymbolAddress((void**)&kt,   g_kt);
    cudaGetSymbolAddress((void**)&vt,   g_vt);
    cudaGetSymbolAddress((void**)&attn, g_attn);
    cudaGetSymbolAddress((void**)&xtf,  g_xtf);
    cudaGetSymbolAddress((void**)&wqt,  g_wqt);
    cudaGetSymbolAddress((void**)&wkt,  g_wkt);
    cudaGetSymbolAddress((void**)&wvt,  g_wvt);
    cudaGetSymbolAddress((void**)&wpt,  g_wpt);

    const int gemm_smem = 2 * (BM + BN) * LDA * 4;          // 61440
    const int attn_smem = (4 * 64 * LDK + 128 * LDK) * 4;   // 110592
    cudaFuncSetAttribute(gemm_qkv,  cudaFuncAttributeMaxDynamicSharedMemorySize, gemm_smem);
    cudaFuncSetAttribute(gemm_proj, cudaFuncAttributeMaxDynamicSharedMemorySize, gemm_smem);
    cudaFuncSetAttribute(attn_tc,   cudaFuncAttributeMaxDynamicSharedMemorySize, attn_smem);

    // single fused tf32 pre-round: x + all 4 weight matrices
    {
        int n4x = M * Ecfg / 4;
        int total = n4x + N4_WQ + N4_WK + N4_WV + N4_WP;
        cvt_all<<<(total + 255) / 256, 256>>>(x, Wq, Wk, Wv, Wproj,
                                              xtf, wqt, wkt, wvt, wpt, n4x);
    }

    gemm_qkv<<<dim3(1536 / BN, M / BM), 256, gemm_smem>>>(xtf, wqt, wkt, wvt, qraw, kraw, vraw, Ecfg);

    rope_rms_kernel<<<dim3(T / 8, Hh, B), 256>>>(qraw, cosb, sinb, qt, T);
    kv_post_kernel <<<dim3(T / 8, HKV, B), 256>>>(kraw, vraw, x, ve, cosb, sinb, Wgate, kt, vt, T);

    attn_tc<<<dim3(T / 64, HKV * 2, B), 256, attn_smem>>>(qt, kt, vt, attn, wsz, T);

    gemm_proj<<<dim3(Ecfg / BN, M / BM), 256, gemm_smem>>>(attn, wpt, (float*)d_out, Ecfg);
}

// round 6
// speedup vs baseline: 1.0223x; 1.0142x over previous
#include <cuda_runtime.h>
#include <mma.h>
#include <cstdint>

using namespace nvcuda;

#define Ecfg 1024
#define Hh   16
#define HKV  4
#define Dd   64

#define BM  128
#define BN  128
#define LDA 40
#define LDK 72

// ---------------- scratch (device globals) ----------------
__device__ float g_qraw[2 * 2048 * 1024];
__device__ float g_kraw[2 * 2048 * 256];
__device__ float g_vraw[2 * 2048 * 256];
__device__ float g_qt  [2 * 16 * 2048 * 64];
__device__ float g_kt  [2 * 4  * 2048 * 64];
__device__ float g_vt  [2 * 4  * 2048 * 64];
__device__ float g_attn[2 * 2048 * 1024];
__device__ float g_xtf [2 * 2048 * 1024];
__device__ float g_wqt [1024 * 1024];
__device__ float g_wkt [256 * 1024];
__device__ float g_wvt [256 * 1024];
__device__ float g_wpt [1024 * 1024];

// ---------------- cp.async helpers ----------------
__device__ __forceinline__ void cp16(float* smem_dst, const float* gsrc) {
    uint32_t s = (uint32_t)__cvta_generic_to_shared(smem_dst);
    asm volatile("cp.async.cg.shared.global [%0], [%1], 16;\n" :: "r"(s), "l"(gsrc));
}
#define CP_COMMIT() asm volatile("cp.async.commit_group;\n" ::: "memory")
#define CP_WAIT1()  asm volatile("cp.async.wait_group 1;\n" ::: "memory")
#define CP_WAIT0()  asm volatile("cp.async.wait_group 0;\n" ::: "memory")

// ---------------- fused tf32 pre-round of x + all weights (1 launch) ----------------
#define N4_WQ 262144
#define N4_WK 65536
#define N4_WV 65536
#define N4_WP 262144
__global__ void cvt_all(const float* __restrict__ x,  const float* __restrict__ wq,
                        const float* __restrict__ wk, const float* __restrict__ wv,
                        const float* __restrict__ wp,
                        float* __restrict__ xo, float* __restrict__ wqo,
                        float* __restrict__ wko, float* __restrict__ wvo,
                        float* __restrict__ wpo, int n4x) {
    int i = blockIdx.x * blockDim.x + threadIdx.x;
    const float4* s; float4* d; int j;
    if (i < n4x) { s = (const float4*)x; d = (float4*)xo; j = i; }
    else {
        i -= n4x;
        if (i < N4_WQ)                          { s = (const float4*)wq; d = (float4*)wqo; j = i; }
        else if (i < N4_WQ + N4_WK)             { s = (const float4*)wk; d = (float4*)wko; j = i - N4_WQ; }
        else if (i < N4_WQ + N4_WK + N4_WV)     { s = (const float4*)wv; d = (float4*)wvo; j = i - N4_WQ - N4_WK; }
        else if (i < N4_WQ + N4_WK + N4_WV + N4_WP) { s = (const float4*)wp; d = (float4*)wpo; j = i - N4_WQ - N4_WK - N4_WV; }
        else return;
    }
    float4 v = s[j];
    v.x = wmma::__float_to_tf32(v.x); v.y = wmma::__float_to_tf32(v.y);
    v.z = wmma::__float_to_tf32(v.z); v.w = wmma::__float_to_tf32(v.w);
    d[j] = v;
}

// ================= TF32 GEMM, cp.async 2-stage: C[M,N] = A @ W^T =================
// BM=BN=128, BK=32, 256 thr = 8 warps (2M x 4N), warp tile 64x32 (acc 4x2).
__device__ __forceinline__ void gemm_core(
    const float* __restrict__ A, const float* __restrict__ W,
    float* __restrict__ C, int N, int K, int m0, int n0) {
    extern __shared__ float sm[];
    float* As = sm;                   // 2 * 128 * LDA
    float* Ws = sm + 2 * BM * LDA;    // 2 * 128 * LDA
    const int tid = threadIdx.x;
    const int warp = tid >> 5;
    const int wm = warp >> 2;   // 0..1 : 64-row strip
    const int wn = warp & 3;    // 0..3 : 32-col strip

    wmma::fragment<wmma::accumulator, 16, 16, 8, float> acc[4][2];
#pragma unroll
    for (int i = 0; i < 4; i++)
#pragma unroll
        for (int j = 0; j < 2; j++) wmma::fill_fragment(acc[i][j], 0.f);

    const float* Ab = A + (size_t)m0 * K;
    const float* Wb = W + (size_t)n0 * K;

#define LOAD_SLAB(it, buf)                                                      \
    {                                                                           \
        const int k0 = (it) << 5;                                               \
        float* ad = As + (buf) * BM * LDA;                                      \
        float* wd = Ws + (buf) * BN * LDA;                                      \
        _Pragma("unroll")                                                       \
        for (int i = 0; i < 4; i++) {                                           \
            int ch = tid + i * 256;                                             \
            int r = ch >> 3, c4 = (ch & 7) << 2;                                \
            cp16(ad + r * LDA + c4, Ab + (size_t)r * K + k0 + c4);              \
            cp16(wd + r * LDA + c4, Wb + (size_t)r * K + k0 + c4);              \
        }                                                                       \
    }

    const int nIter = K >> 5;
    LOAD_SLAB(0, 0); CP_COMMIT();
    for (int it = 0; it < nIter; ++it) {
        const int buf = it & 1;
        if (it + 1 < nIter) { LOAD_SLAB(it + 1, buf ^ 1); CP_COMMIT(); CP_WAIT1(); }
        else CP_WAIT0();
        __syncthreads();
        const float* as = As + buf * BM * LDA;
        const float* ws = Ws + buf * BN * LDA;
#pragma unroll
        for (int kk = 0; kk < 32; kk += 8) {
            wmma::fragment<wmma::matrix_a, 16, 16, 8, wmma::precision::tf32, wmma::row_major> a[4];
            wmma::fragment<wmma::matrix_b, 16, 16, 8, wmma::precision::tf32, wmma::col_major> b[2];
#pragma unroll
            for (int i = 0; i < 4; i++)
                wmma::load_matrix_sync(a[i], &as[(wm * 64 + i * 16) * LDA + kk], LDA);
#pragma unroll
            for (int j = 0; j < 2; j++)
                wmma::load_matrix_sync(b[j], &ws[(wn * 32 + j * 16) * LDA + kk], LDA);
#pragma unroll
            for (int i = 0; i < 4; i++)
#pragma unroll
                for (int j = 0; j < 2; j++)
                    wmma::mma_sync(acc[i][j], a[i], b[j], acc[i][j]);
        }
        __syncthreads();
    }
#undef LOAD_SLAB
#pragma unroll
    for (int i = 0; i < 4; i++)
#pragma unroll
        for (int j = 0; j < 2; j++)
            wmma::store_matrix_sync(&C[(size_t)(m0 + wm * 64 + i * 16) * N + n0 + wn * 32 + j * 16],
                                    acc[i][j], N, wmma::mem_row_major);
}

__global__ __launch_bounds__(256, 2) void gemm_proj(
    const float* __restrict__ A, const float* __restrict__ W, float* __restrict__ C, int K) {
    gemm_core(A, W, C, Ecfg, K, blockIdx.y * BM, blockIdx.x * BN);
}

// fused QKV: 12 n-tiles = 8 (Q, N=1024) + 2 (K, N=256) + 2 (V, N=256)
__global__ __launch_bounds__(256, 2) void gemm_qkv(
    const float* __restrict__ x,
    const float* __restrict__ Wq, const float* __restrict__ Wk, const float* __restrict__ Wv,
    float* __restrict__ Cq, float* __restrict__ Ck, float* __restrict__ Cv, int K) {
    const int ng = blockIdx.x * BN;
    const float* W; float* C; int N, n0;
    if (ng < 1024)      { W = Wq; C = Cq; N = 1024; n0 = ng; }
    else if (ng < 1280) { W = Wk; C = Ck; N = 256;  n0 = ng - 1024; }
    else                { W = Wv; C = Cv; N = 256;  n0 = ng - 1280; }
    gemm_core(x, W, C, N, K, blockIdx.y * BM, n0);
}

// ---------------- rope + rmsnorm for Q (writes tf32-rounded) ----------------
__global__ void rope_rms_kernel(const float* __restrict__ raw,
                                const float* __restrict__ cosb,
                                const float* __restrict__ sinb,
                                float* __restrict__ dst, int T) {
    const int warp = threadIdx.x >> 5, lane = threadIdx.x & 31;
    const int t = blockIdx.x * 8 + warp;
    const int h = blockIdx.y, b = blockIdx.z;
    const int NH = gridDim.y;
    const float* src = raw + (((size_t)b * T + t) * NH + h) * 64;
    float x1 = src[lane], x2 = src[32 + lane];
    float c = cosb[(size_t)t * 32 + lane];
    float s = sinb[(size_t)t * 32 + lane];
    float r1 = x1 * c + x2 * s;
    float r2 = x2 * c - x1 * s;
    float ss = r1 * r1 + r2 * r2;
#pragma unroll
    for (int o = 16; o; o >>= 1) ss += __shfl_xor_sync(0xffffffffu, ss, o);
    float inv = rsqrtf(ss * (1.f / 64.f) + 1.1920929e-07f);
    float* d = dst + (((size_t)b * NH + h) * T + t) * 64;
    d[lane] = wmma::__float_to_tf32(r1 * inv);
    d[32 + lane] = wmma::__float_to_tf32(r2 * inv);
}

// ---------------- fused K rope+rms AND V gate (writes tf32-rounded) ----------------
__global__ void kv_post_kernel(const float* __restrict__ kraw,
                               const float* __restrict__ vraw,
                               const float* __restrict__ x,
                               const float* __restrict__ ve,
                               const float* __restrict__ cosb,
                               const float* __restrict__ sinb,
                               const float* __restrict__ Wgate,
                               float* __restrict__ k_t,
                               float* __restrict__ v_t, int T) {
    const int warp = threadIdx.x >> 5, lane = threadIdx.x & 31;
    const int t = blockIdx.x * 8 + warp;
    const int h = blockIdx.y, b = blockIdx.z;
    const size_t tok = (size_t)b * T + t;
    {
        const float* src = kraw + (tok * HKV + h) * 64;
        float x1 = src[lane], x2 = src[32 + lane];
        float c = cosb[(size_t)t * 32 + lane];
        float s = sinb[(size_t)t * 32 + lane];
        float r1 = x1 * c + x2 * s;
        float r2 = x2 * c - x1 * s;
        float ss = r1 * r1 + r2 * r2;
#pragma unroll
        for (int o = 16; o; o >>= 1) ss += __shfl_xor_sync(0xffffffffu, ss, o);
        float inv = rsqrtf(ss * (1.f / 64.f) + 1.1920929e-07f);
        float* d = k_t + (((size_t)b * HKV + h) * T + t) * 64;
        d[lane] = wmma::__float_to_tf32(r1 * inv);
        d[32 + lane] = wmma::__float_to_tf32(r2 * inv);
    }
    {
        float g = x[tok * Ecfg + lane] * Wgate[h * 32 + lane];
#pragma unroll
        for (int o = 16; o; o >>= 1) g += __shfl_xor_sync(0xffffffffu, g, o);
        float gate = 2.f / (1.f + __expf(-g));
        const float* vs = vraw + (tok * HKV + h) * 64;
        const float* ves = ve + (tok * HKV + h) * 64;
        float* d = v_t + (((size_t)b * HKV + h) * T + t) * 64;
        d[lane] = wmma::__float_to_tf32(vs[lane] + gate * ves[lane]);
        d[32 + lane] = wmma::__float_to_tf32(vs[32 + lane] + gate * ves[32 + lane]);
    }
}

// ================ sliding-window flash attention: 32-row warps ================
// 128 thr = 4 warps; warp w owns query rows [32w, 32w+32) of a 128-row Q tile.
// Each K/V fragment load feeds TWO 16-row strips -> halved LDS per FLOP.
// K/V double-buffered via cp.async. Fixed-max softmax (scores <= 8 after
// rmsnorm + 1/8 scale). O persists in accumulator fragments.
__global__ __launch_bounds__(128, 2) void attn_tc(
    const float* __restrict__ q, const float* __restrict__ k,
    const float* __restrict__ v, float* __restrict__ out,
    const int* __restrict__ wptr, int T) {
    extern __shared__ float sm[];
    float* Ks = sm;                    // 2 * 64 * LDK
    float* Vs = sm + 2 * 64 * LDK;     // 2 * 64 * LDK
    float* Ss = sm + 4 * 64 * LDK;     // 128 * LDK

    const int qtile = blockIdx.x, h = blockIdx.y, b = blockIdx.z;
    const int W = wptr[0];
    const int tid = threadIdx.x;
    const int warp = tid >> 5, lane = tid & 31;
    const int qbase = qtile * 128;
    const int half = lane & 1;

    // persistent Q fragments: 2 strips x 8 k-frags (tf32 pre-rounded; *0.125 exact)
    wmma::fragment<wmma::matrix_a, 16, 16, 8, wmma::precision::tf32, wmma::row_major> qf[2][8];
#pragma unroll
    for (int i = 0; i < 2; i++) {
        const float* qptr = q + ((size_t)(b * Hh + h) * T + qbase + warp * 32 + i * 16) * Dd;
#pragma unroll
        for (int kk = 0; kk < 8; kk++) {
            wmma::load_matrix_sync(qf[i][kk], qptr + kk * 8, Dd);
#pragma unroll
            for (int e = 0; e < qf[i][kk].num_elements; e++)
                qf[i][kk].x[e] *= 0.125f;
        }
    }
    wmma::fragment<wmma::accumulator, 16, 16, 8, float> oa[2][4];
#pragma unroll
    for (int i = 0; i < 2; i++)
#pragma unroll
        for (int j = 0; j < 4; j++) wmma::fill_fragment(oa[i][j], 0.f);

    const int hkv = h >> 2;
    const float* kb = k + (size_t)(b * HKV + hkv) * T * Dd;
    const float* vb = v + (size_t)(b * HKV + hkv) * T * Dd;
    int kmin = qbase - W; if (kmin < 0) kmin = 0;
    const int t0 = kmin >> 6;
    const int ktend = 2 * qtile + 1;   // last 64-key tile overlapping this Q tile

#define LOAD_KV(kt, buf)                                                        \
    {                                                                           \
        const float* kp = kb + (size_t)(kt) * 64 * Dd;                          \
        const float* vp = vb + (size_t)(kt) * 64 * Dd;                          \
        float* kd = Ks + (buf) * 64 * LDK;                                      \
        float* vd = Vs + (buf) * 64 * LDK;                                      \
        _Pragma("unroll")                                                       \
        for (int i = 0; i < 8; i++) {                                           \
            int ch = tid + i * 128;                                             \
            int r = ch >> 4, c4 = (ch & 15) << 2;                               \
            cp16(kd + r * LDK + c4, kp + r * 64 + c4);                          \
            cp16(vd + r * LDK + c4, vp + r * 64 + c4);                          \
        }                                                                       \
    }

    LOAD_KV(t0, 0); CP_COMMIT();
    float l_run[2] = {0.f, 0.f};

    for (int kt = t0; kt <= ktend; ++kt) {
        const int buf = (kt - t0) & 1;
        if (kt < ktend) { LOAD_KV(kt + 1, buf ^ 1); CP_COMMIT(); CP_WAIT1(); }
        else CP_WAIT0();
        __syncthreads();
        const float* ks = Ks + buf * 64 * LDK;
        const float* vs = Vs + buf * 64 * LDK;

        // S = Q @ K^T : 32x64 per warp, K-frag shared across the 2 row strips
        {
            wmma::fragment<wmma::accumulator, 16, 16, 8, float> sa[2][4];
#pragma unroll
            for (int i = 0; i < 2; i++)
#pragma unroll
                for (int j = 0; j < 4; j++) wmma::fill_fragment(sa[i][j], 0.f);
#pragma unroll
            for (int kk = 0; kk < 8; kk++) {
#pragma unroll
                for (int j = 0; j < 4; j++) {
                    wmma::fragment<wmma::matrix_b, 16, 16, 8, wmma::precision::tf32, wmma::col_major> bf;
                    wmma::load_matrix_sync(bf, &ks[(j * 16) * LDK + kk * 8], LDK);
                    wmma::mma_sync(sa[0][j], qf[0][kk], bf, sa[0][j]);
                    wmma::mma_sync(sa[1][j], qf[1][kk], bf, sa[1][j]);
                }
            }
#pragma unroll
            for (int i = 0; i < 2; i++)
#pragma unroll
                for (int j = 0; j < 4; j++)
                    wmma::store_matrix_sync(&Ss[(warp * 32 + i * 16) * LDK + j * 16],
                                            sa[i][j], LDK, wmma::mem_row_major);
        }
        __syncwarp();

        // fixed-max softmax: two 16-row passes, 2 lanes per row
        {
#pragma unroll
            for (int p = 0; p < 2; p++) {
                const int sRow = warp * 32 + p * 16 + (lane >> 1);
                const int qrow = qbase + sRow;
                float* srow = &Ss[sRow * LDK + half * 32];
                float lloc = 0.f;
#pragma unroll
                for (int c = 0; c < 32; c++) {
                    int col = (kt << 6) + (half << 5) + c;
                    float pv = 0.f;
                    if (col <= qrow && col >= qrow - W) {
                        pv = __expf(srow[c] - 8.f);
                        lloc += pv;
                    }
                    srow[c] = wmma::__float_to_tf32(pv);
                }
                l_run[p] += lloc;
            }
        }
        __syncwarp();

        // O += P @ V : V-frag shared across the 2 row strips
#pragma unroll
        for (int kk = 0; kk < 8; kk++) {
            wmma::fragment<wmma::matrix_a, 16, 16, 8, wmma::precision::tf32, wmma::row_major> pf[2];
#pragma unroll
            for (int i = 0; i < 2; i++)
                wmma::load_matrix_sync(pf[i], &Ss[(warp * 32 + i * 16) * LDK + kk * 8], LDK);
#pragma unroll
            for (int j = 0; j < 4; j++) {
                wmma::fragment<wmma::matrix_b, 16, 16, 8, wmma::precision::tf32, wmma::row_major> bf;
                wmma::load_matrix_sync(bf, &vs[(kk * 8) * LDK + j * 16], LDK);
                wmma::mma_sync(oa[0][j], pf[0], bf, oa[0][j]);
                wmma::mma_sync(oa[1][j], pf[1], bf, oa[1][j]);
            }
        }
        __syncthreads();
    }
#undef LOAD_KV

    // epilogue: stage O, normalize per row, write tf32-rounded [B,T,H,D]
#pragma unroll
    for (int i = 0; i < 2; i++)
#pragma unroll
        for (int j = 0; j < 4; j++)
            wmma::store_matrix_sync(&Ss[(warp * 32 + i * 16) * LDK + j * 16],
                                    oa[i][j], LDK, wmma::mem_row_major);
    __syncwarp();
#pragma unroll
    for (int p = 0; p < 2; p++) {
        const int sRow = warp * 32 + p * 16 + (lane >> 1);
        const int qrow = qbase + sRow;
        float l_tot = l_run[p] + __shfl_xor_sync(0xffffffffu, l_run[p], 1);
        float inv = 1.f / l_tot;
        float* op = out + ((size_t)(b * T + qrow) * Hh + h) * Dd + half * 32;
        const float* orow = &Ss[sRow * LDK + half * 32];
#pragma unroll
        for (int c = 0; c < 32; c += 4) {
            float4 o = make_float4(wmma::__float_to_tf32(orow[c] * inv),
                                   wmma::__float_to_tf32(orow[c + 1] * inv),
                                   wmma::__float_to_tf32(orow[c + 2] * inv),
                                   wmma::__float_to_tf32(orow[c + 3] * inv));
            *reinterpret_cast<float4*>(&op[c]) = o;
        }
    }
}

// ---------------- launch ----------------
extern "C" void kernel_launch(void* const* d_in, const int* in_sizes, int n_in,
                              void* d_out, int out_size) {
    const float* x     = (const float*)d_in[0];
    const float* ve    = (const float*)d_in[1];
    const float* cosb  = (const float*)d_in[2];
    const float* sinb  = (const float*)d_in[3];
    const float* Wq    = (const float*)d_in[4];
    const float* Wk    = (const float*)d_in[5];
    const float* Wv    = (const float*)d_in[6];
    const float* Wproj = (const float*)d_in[7];
    const float* Wgate = (const float*)d_in[8];
    const int*   wsz   = (const int*)d_in[9];

    int T = in_sizes[2] / 32;
    int B = in_sizes[0] / (T * Ecfg);
    int M = B * T;

    float *qraw, *kraw, *vraw, *qt, *kt, *vt, *attn;
    float *xtf, *wqt, *wkt, *wvt, *wpt;
    cudaGetSymbolAddress((void**)&qraw, g_qraw);
    cudaGetSymbolAddress((void**)&kraw, g_kraw);
    cudaGetSymbolAddress((void**)&vraw, g_vraw);
    cudaGetSymbolAddress((void**)&qt,   g_qt);
    cudaGetSymbolAddress((void**)&kt,   g_kt);
    cudaGetSymbolAddress((void**)&vt,   g_vt);
    cudaGetSymbolAddress((void**)&attn, g_attn);
    cudaGetSymbolAddress((void**)&xtf,  g_xtf);
    cudaGetSymbolAddress((void**)&wqt,  g_wqt);
    cudaGetSymbolAddress((void**)&wkt,  g_wkt);
    cudaGetSymbolAddress((void**)&wvt,  g_wvt);
    cudaGetSymbolAddress((void**)&wpt,  g_wpt);

    const int gemm_smem = 2 * (BM + BN) * LDA * 4;          // 81920
    const int attn_smem = (4 * 64 * LDK + 128 * LDK) * 4;   // 110592
    cudaFuncSetAttribute(gemm_qkv,  cudaFuncAttributeMaxDynamicSharedMemorySize, gemm_smem);
    cudaFuncSetAttribute(gemm_proj, cudaFuncAttributeMaxDynamicSharedMemorySize, gemm_smem);
    cudaFuncSetAttribute(attn_tc,   cudaFuncAttributeMaxDynamicSharedMemorySize, attn_smem);

    // single fused tf32 pre-round: x + all 4 weight matrices
    {
        int n4x = M * Ecfg / 4;
        int total = n4x + N4_WQ + N4_WK + N4_WV + N4_WP;
        cvt_all<<<(total + 255) / 256, 256>>>(x, Wq, Wk, Wv, Wproj,
                                              xtf, wqt, wkt, wvt, wpt, n4x);
    }

    gemm_qkv<<<dim3(1536 / BN, M / BM), 256, gemm_smem>>>(xtf, wqt, wkt, wvt, qraw, kraw, vraw, Ecfg);

    rope_rms_kernel<<<dim3(T / 8, Hh, B), 256>>>(qraw, cosb, sinb, qt, T);
    kv_post_kernel <<<dim3(T / 8, HKV, B), 256>>>(kraw, vraw, x, ve, cosb, sinb, Wgate, kt, vt, T);

    attn_tc<<<dim3(T / 128, Hh, B), 128, attn_smem>>>(qt, kt, vt, attn, wsz, T);

    gemm_proj<<<dim3(Ecfg / BN, M / BM), 256, gemm_smem>>>(attn, wpt, (float*)d_out, Ecfg);
}